// round 8
// baseline (speedup 1.0000x reference)
#include <cuda_runtime.h>
#include <cuda_bf16.h>
#include <cstdint>
#include <math.h>

// ---------------- problem constants ----------------
#define LSEQ   4096
#define DM     256
#define DI     512
#define DS     16
#define DTR    16
#define NXP    48
#define NXPAD  64
#define DCONV  4
#define NC     64
#define CLEN   64
#define LN_EPS 1e-5f

typedef __nv_bfloat16 bf16;

// ---------------- device scratch ----------------
__device__ float g_part[8*LSEQ*DM];        // split-K partials
__device__ float g_h1  [LSEQ*DM];
__device__ float g_xz  [LSEQ*2*DI];
__device__ float g_u   [LSEQ*DI];
__device__ float g_wxpp[DI*NXPAD];
__device__ float g_dbc [LSEQ*NXPAD];
__device__ float g_dt  [LSEQ*DI];
__device__ float g_cP  [NC*DI*DS];
__device__ float g_cS  [NC*DI*DS];
__device__ float g_hin [NC*DI*DS];

// bf16 hi/lo operand copies
__device__ bf16 g_adjh[LSEQ*LSEQ],  g_adjl[LSEQ*LSEQ];      // A of adj@x (64MB)
__device__ bf16 g_t0h [LSEQ*DM],    g_t0l [LSEQ*DM];        // A of gcn
__device__ bf16 g_hlnh[LSEQ*DM],    g_hlnl[LSEQ*DM];        // A of xz
__device__ bf16 g_uh  [LSEQ*DI],    g_ul  [LSEQ*DI];        // A of dbc
__device__ bf16 g_ygh [LSEQ*DI],    g_ygl [LSEQ*DI];        // A of out
// packed B operands: [K/2][N] u32, word = {bf16 k-even, bf16 k-odd}
__device__ uint32_t g_xph [LSEQ/2*DM],     g_xpl [LSEQ/2*DM];
__device__ uint32_t g_gwh [DM/2*DM],       g_gwl [DM/2*DM];
__device__ uint32_t g_wih [DM/2*2*DI],     g_wil [DM/2*2*DI];
__device__ uint32_t g_wxh [DI/2*NXPAD],    g_wxl [DI/2*NXPAD];
__device__ uint32_t g_woh [DI/2*DM],       g_wol [DI/2*DM];

// ================= helpers =================
__device__ __forceinline__ uint32_t smem_u32(const void* p) {
    uint32_t a;
    asm("{ .reg .u64 t; cvta.to.shared.u64 t, %1; cvt.u32.u64 %0, t; }" : "=r"(a) : "l"(p));
    return a;
}

#define CP_ASYNC16(dst, src) \
    asm volatile("cp.async.cg.shared.global [%0], [%1], 16;" :: "r"(dst), "l"(src))
#define CP_COMMIT() asm volatile("cp.async.commit_group;" ::: "memory")
#define CP_WAIT1()  asm volatile("cp.async.wait_group 1;"  ::: "memory")

#define LDMATRIX_X4(r, addr) \
    asm volatile("ldmatrix.sync.aligned.m8n8.x4.shared.b16 {%0,%1,%2,%3}, [%4];" \
        : "=r"((r)[0]), "=r"((r)[1]), "=r"((r)[2]), "=r"((r)[3]) : "r"(addr))

#define MMA_BF16(c, a, b) \
    asm volatile("mma.sync.aligned.m16n8k16.row.col.f32.bf16.bf16.f32 " \
        "{%0,%1,%2,%3},{%4,%5,%6,%7},{%8,%9},{%0,%1,%2,%3};" \
        : "+f"((c)[0]), "+f"((c)[1]), "+f"((c)[2]), "+f"((c)[3]) \
        : "r"((a)[0]), "r"((a)[1]), "r"((a)[2]), "r"((a)[3]), "r"((b)[0]), "r"((b)[1]))

__device__ __forceinline__ uint32_t pack2(float e0, float e1) {
    __nv_bfloat162 v = __floats2bfloat162_rn(e0, e1);
    return *(uint32_t*)&v;
}
__device__ __forceinline__ void split1(float v, float& hi, float& lo) {
    bf16 h = __float2bfloat16_rn(v);
    hi = __bfloat162float(h);
    lo = v - hi;
}
__device__ __forceinline__ void split_bf(float v, bf16& h, bf16& l) {
    h = __float2bfloat16_rn(v);
    l = __float2bfloat16_rn(v - __bfloat162float(h));
}

// ================= bf16x3 GEMM, pre-split operands, cp.async 3-stage =================
// C = Ahi*Bhi + Ahi*Blo + Alo*Bhi. Block 128x64, BK=32, 8 warps (2M x 4N).
#define BM 128
#define BN 64
#define BK 32
#define ASTR   40                            // bf16 per A smem row (80B = 5x16B)
#define BSTRW  72                            // u32 words per B k2-row (288B = 18x16B)
#define A_LO_OFF (BM*ASTR*2)                 // 10240
#define B_HI_OFF (2*BM*ASTR*2)               // 20480
#define B_LO_OFF (B_HI_OFF + 16*BSTRW*4)     // 25088
#define STAGE_B  (B_LO_OFF + 16*BSTRW*4)     // 29696
#define NSTAGE   3
#define MMA_SMEM (NSTAGE*STAGE_B)            // 89088

__global__ __launch_bounds__(256)
void mma_gemm(const bf16* __restrict__ Ah, const bf16* __restrict__ Al,
              const uint32_t* __restrict__ Bh, const uint32_t* __restrict__ Bl,
              float* __restrict__ C, int K, int Ng, int lda, size_t csplit)
{
    extern __shared__ char smem[];
    const uint32_t sb = smem_u32(smem);
    const int tid  = threadIdx.x;
    const int wid  = tid >> 5, lane = tid & 31;
    const int warpM = wid & 1, warpN = wid >> 1;
    const int m0 = blockIdx.y * BM;
    const int n0 = blockIdx.x * BN;
    const int z  = blockIdx.z;
    const int g  = lane >> 2, tg = lane & 3;

    const bf16* Azh = Ah + (size_t)z * K;               // column offset
    const bf16* Azl = Al + (size_t)z * K;
    const uint32_t* Bzh = Bh + (size_t)z * (K / 2) * Ng;  // row offset (words)
    const uint32_t* Bzl = Bl + (size_t)z * (K / 2) * Ng;
    float* Cz = C + (size_t)z * csplit;
    const int nch = K / BK;

    // staging indices
    const int ar  = tid >> 2;            // A row 0..63 (+64)
    const int as8 = (tid & 3) * 8;       // A col seg (bf16 idx)
    const int br  = tid >> 4;            // B k2-row 0..15
    const int bc4 = (tid & 15) * 4;      // B word col

    auto issue = [&](int c, int s) {
        const int k0 = c * BK;
        const uint32_t base = sb + (uint32_t)s * STAGE_B;
#pragma unroll
        for (int i = 0; i < 2; i++) {
            const int row = ar + 64 * i;
            const uint32_t dst = base + (uint32_t)(row * ASTR + as8) * 2;
            const size_t goff = (size_t)(m0 + row) * lda + k0 + as8;
            CP_ASYNC16(dst,            Azh + goff);
            CP_ASYNC16(dst + A_LO_OFF, Azl + goff);
        }
        {
            const uint32_t dsth = base + B_HI_OFF + (uint32_t)(br * BSTRW + bc4) * 4;
            const uint32_t dstl = base + B_LO_OFF + (uint32_t)(br * BSTRW + bc4) * 4;
            const size_t goff = (size_t)(k0 / 2 + br) * Ng + n0 + bc4;
            CP_ASYNC16(dsth, Bzh + goff);
            CP_ASYNC16(dstl, Bzl + goff);
        }
    };

    float c[4][2][4];
#pragma unroll
    for (int mt = 0; mt < 4; mt++)
#pragma unroll
        for (int nt = 0; nt < 2; nt++)
#pragma unroll
            for (int i = 0; i < 4; i++) c[mt][nt][i] = 0.f;

    const uint32_t aHiOff = (uint32_t)((warpM * 64 + (lane & 15)) * ASTR + (lane >> 4) * 8) * 2;

    issue(0, 0); CP_COMMIT();
    if (nch > 1) issue(1, 1);
    CP_COMMIT();

    for (int ch = 0; ch < nch; ch++) {
        CP_WAIT1();
        __syncthreads();
        if (ch + 2 < nch) issue(ch + 2, (ch + 2) % NSTAGE);
        CP_COMMIT();                      // uniform group accounting

        const int st = ch % NSTAGE;
        const char* base = smem + st * STAGE_B;
        const uint32_t aB = sb + st * STAGE_B + aHiOff;
        const uint32_t* bh = (const uint32_t*)(base + B_HI_OFF);
        const uint32_t* bl = (const uint32_t*)(base + B_LO_OFF);
#pragma unroll
        for (int kh = 0; kh < 2; kh++) {
            uint32_t bhi[2][2], blo[2][2];
#pragma unroll
            for (int nt = 0; nt < 2; nt++) {
                const int w = (kh * 8 + tg) * BSTRW + warpN * 16 + nt * 8 + g;
                bhi[nt][0] = bh[w];  bhi[nt][1] = bh[w + 4 * BSTRW];
                blo[nt][0] = bl[w];  blo[nt][1] = bl[w + 4 * BSTRW];
            }
#pragma unroll
            for (int mt = 0; mt < 4; mt++) {
                uint32_t ah[4], al[4];
                const uint32_t off = (uint32_t)(mt * 16 * ASTR + kh * 16) * 2;
                LDMATRIX_X4(ah, aB + off);
                LDMATRIX_X4(al, aB + A_LO_OFF + off);
#pragma unroll
                for (int nt = 0; nt < 2; nt++) {
                    MMA_BF16(c[mt][nt], ah, bhi[nt]);
                    MMA_BF16(c[mt][nt], ah, blo[nt]);
                    MMA_BF16(c[mt][nt], al, bhi[nt]);
                }
            }
        }
    }

    // ---- epilogue ----
#pragma unroll
    for (int mt = 0; mt < 4; mt++)
#pragma unroll
        for (int nt = 0; nt < 2; nt++) {
            const int row = m0 + warpM * 64 + mt * 16 + g;
            const int col = n0 + warpN * 16 + nt * 8 + 2 * tg;
            *(float2*)(Cz + (size_t)row * Ng + col)       = make_float2(c[mt][nt][0], c[mt][nt][1]);
            *(float2*)(Cz + (size_t)(row + 8) * Ng + col) = make_float2(c[mt][nt][2], c[mt][nt][3]);
        }
}

// ---------------- converters ----------------
// A-layout: fp32 [M][K] -> bf16 hi/lo [M][K]
__global__ __launch_bounds__(256)
void cvtA_k(const float* __restrict__ A, bf16* __restrict__ Ah, bf16* __restrict__ Al)
{
    const size_t i = ((size_t)blockIdx.x * 256 + threadIdx.x) * 4;
    float4 v = *(const float4*)(A + i);
    bf16 h[4], l[4];
    split_bf(v.x, h[0], l[0]); split_bf(v.y, h[1], l[1]);
    split_bf(v.z, h[2], l[2]); split_bf(v.w, h[3], l[3]);
    *(uint2*)(Ah + i) = *(uint2*)h;
    *(uint2*)(Al + i) = *(uint2*)l;
}

// B-layout: fp32 [K][N] -> packed u32 [K/2][N] hi/lo
__global__ __launch_bounds__(256)
void cvtB_k(const float* __restrict__ B, uint32_t* __restrict__ Bh,
            uint32_t* __restrict__ Bl, int N)
{
    const size_t i = ((size_t)blockIdx.x * 256 + threadIdx.x) * 4;  // word index
    const int k2 = (int)(i / N), n = (int)(i % N);
    float4 a = *(const float4*)(B + (size_t)(2 * k2)     * N + n);
    float4 b = *(const float4*)(B + (size_t)(2 * k2 + 1) * N + n);
    const float* ea = &a.x;
    const float* eb = &b.x;
    uint32_t hw[4], lw[4];
#pragma unroll
    for (int j = 0; j < 4; j++) {
        float h0, l0, h1, l1;
        split1(ea[j], h0, l0);
        split1(eb[j], h1, l1);
        hw[j] = pack2(h0, h1);
        lw[j] = pack2(l0, l1);
    }
    *(uint4*)(Bh + i) = *(uint4*)hw;
    *(uint4*)(Bl + i) = *(uint4*)lw;
}

// ---------------- split-K reductions ----------------
__global__ __launch_bounds__(256)
void reduce_k(const float* __restrict__ p, float* __restrict__ out,
              size_t stride, int count)
{
    const size_t i = ((size_t)blockIdx.x * 256 + threadIdx.x) * 4;
    float4 s = *(const float4*)(p + i);
    for (int cc = 1; cc < count; cc++) {
        float4 v = *(const float4*)(p + cc * stride + i);
        s.x += v.x; s.y += v.y; s.z += v.z; s.w += v.w;
    }
    *(float4*)(out + i) = s;
}

// reduce 8 partials -> bf16 hi/lo (t0 for gcn GEMM)
__global__ __launch_bounds__(256)
void reduce_bf_k(const float* __restrict__ p, bf16* __restrict__ oh,
                 bf16* __restrict__ ol, size_t stride, int count)
{
    const size_t i = ((size_t)blockIdx.x * 256 + threadIdx.x) * 4;
    float4 s = *(const float4*)(p + i);
    for (int cc = 1; cc < count; cc++) {
        float4 v = *(const float4*)(p + cc * stride + i);
        s.x += v.x; s.y += v.y; s.z += v.z; s.w += v.w;
    }
    bf16 h[4], l[4];
    split_bf(s.x, h[0], l[0]); split_bf(s.y, h[1], l[1]);
    split_bf(s.z, h[2], l[2]); split_bf(s.w, h[3], l[3]);
    *(uint2*)(oh + i) = *(uint2*)h;
    *(uint2*)(ol + i) = *(uint2*)l;
}

// ---------------- gcn finish: h1 = relu(part0 + part1 + bias) ----------------
__global__ __launch_bounds__(256)
void gcnfin_k(const float* __restrict__ p, const float* __restrict__ bias,
              float* __restrict__ h1)
{
    const size_t i = ((size_t)blockIdx.x * 256 + threadIdx.x) * 4;
    const int col = (int)(i & (DM - 1));
    float4 a = *(const float4*)(p + i);
    float4 b = *(const float4*)(p + (size_t)LSEQ * DM + i);
    float4 o;
    o.x = fmaxf(a.x + b.x + bias[col],     0.f);
    o.y = fmaxf(a.y + b.y + bias[col + 1], 0.f);
    o.z = fmaxf(a.z + b.z + bias[col + 2], 0.f);
    o.w = fmaxf(a.w + b.w + bias[col + 3], 0.f);
    *(float4*)(h1 + i) = o;
}

// ---------------- pad w_xp ----------------
__global__ __launch_bounds__(256)
void padw_k(const float* __restrict__ wxp, float* __restrict__ wxpp)
{
    const int i = blockIdx.x * 256 + threadIdx.x;
    const int r = i >> 6, col = i & 63;
    wxpp[i] = (col < NXP) ? wxp[r * NXP + col] : 0.f;
}

// ---------------- layernorm (emits bf16 hi/lo) ----------------
__global__ __launch_bounds__(256)
void ln_k(const float* __restrict__ h1, const float* __restrict__ g,
          const float* __restrict__ b, bf16* __restrict__ oh, bf16* __restrict__ ol)
{
    const int row = blockIdx.x;
    const int tid = threadIdx.x;
    float v = h1[(size_t)row * DM + tid];
    float s = v, s2 = v * v;
#pragma unroll
    for (int o = 16; o; o >>= 1) {
        s  += __shfl_xor_sync(0xffffffffu, s,  o);
        s2 += __shfl_xor_sync(0xffffffffu, s2, o);
    }
    __shared__ float ws[8], ws2[8];
    if ((tid & 31) == 0) { ws[tid >> 5] = s; ws2[tid >> 5] = s2; }
    __syncthreads();
    float ts = 0.f, ts2 = 0.f;
#pragma unroll
    for (int i = 0; i < 8; i++) { ts += ws[i]; ts2 += ws2[i]; }
    const float mu  = ts * (1.f / DM);
    const float var = ts2 * (1.f / DM) - mu * mu;
    const float r   = rsqrtf(var + LN_EPS);
    const float o   = (v - mu) * r * g[tid] + b[tid];
    bf16 h, l;
    split_bf(o, h, l);
    oh[(size_t)row * DM + tid] = h;
    ol[(size_t)row * DM + tid] = l;
}

// ---------------- conv + silu (emits fp32 + bf16 hi/lo) ----------------
__global__ __launch_bounds__(256)
void conv_silu_k(const float* __restrict__ xz, const float* __restrict__ cw,
                 const float* __restrict__ cb, float* __restrict__ u,
                 bf16* __restrict__ uh, bf16* __restrict__ ul)
{
    const int idx = blockIdx.x * 256 + threadIdx.x;
    const int l = idx >> 9, d = idx & (DI - 1);
    float s = cb[d];
#pragma unroll
    for (int k = 0; k < DCONV; k++) {
        const int ls = l - (DCONV - 1) + k;
        if (ls >= 0) s += xz[(size_t)ls * (2 * DI) + d] * cw[d * DCONV + k];
    }
    const float sig = 1.f / (1.f + __expf(-s));
    const float v = s * sig;
    u[idx] = v;
    bf16 h, lo;
    split_bf(v, h, lo);
    uh[idx] = h;
    ul[idx] = lo;
}

// ---------------- dt ----------------
__global__ __launch_bounds__(256)
void dt_k(const float* __restrict__ dbc, const float* __restrict__ wdt,
          const float* __restrict__ bdt, float* __restrict__ dt)
{
    const int idx = blockIdx.x * 256 + threadIdx.x;
    const int l = idx >> 9, d = idx & (DI - 1);
    float s = bdt[d];
    const float* dr = dbc + (size_t)l * NXPAD;
#pragma unroll
    for (int k = 0; k < DTR; k++) s += dr[k] * wdt[k * DI + d];
    dt[idx] = (s > 20.f) ? s : log1pf(__expf(s));
}

// ---------------- scan phase 1 ----------------
__global__ __launch_bounds__(512)
void scan1_k(const float* __restrict__ dt, const float* __restrict__ u,
             const float* __restrict__ dbc, const float* __restrict__ Alog,
             float* __restrict__ cP, float* __restrict__ cS)
{
    const int t = threadIdx.x;
    const int dl = t >> 4, s = t & 15;
    const int d = blockIdx.x * 32 + dl;
    const int c = blockIdx.y;
    const float A = -__expf(Alog[d * DS + s]);
    const int l0 = c * CLEN;
    const float* pdt = dt  + (size_t)l0 * DI + d;
    const float* pu  = u   + (size_t)l0 * DI + d;
    const float* pB  = dbc + (size_t)l0 * NXPAD + DTR + s;
    float P = 1.f, S = 0.f;
#pragma unroll 4
    for (int i = 0; i < CLEN; i++) {
        const float dtv = pdt[i * DI];
        const float uv  = pu [i * DI];
        const float Bv  = pB [i * NXPAD];
        const float a = __expf(A * dtv);
        const float b = dtv * Bv * uv;
        P *= a;
        S = a * S + b;
    }
    const int idx = d * DS + s;
    cP[(size_t)c * (DI * DS) + idx] = P;
    cS[(size_t)c * (DI * DS) + idx] = S;
}

// ---------------- scan phase 2 ----------------
__global__ __launch_bounds__(512)
void scan2_k(const float* __restrict__ cP, const float* __restrict__ cS,
             float* __restrict__ hin)
{
    const int idx = blockIdx.x * 512 + threadIdx.x;
    float h = 0.f;
#pragma unroll 4
    for (int c = 0; c < NC; c++) {
        hin[(size_t)c * (DI * DS) + idx] = h;
        h = cP[(size_t)c * (DI * DS) + idx] * h + cS[(size_t)c * (DI * DS) + idx];
    }
}

// ---------------- scan phase 3 (emits yg bf16 hi/lo) ----------------
__global__ __launch_bounds__(512)
void scan3_k(const float* __restrict__ dt, const float* __restrict__ u,
             const float* __restrict__ dbc, const float* __restrict__ Alog,
             const float* __restrict__ hin, const float* __restrict__ xz,
             const float* __restrict__ Dskip,
             bf16* __restrict__ ygh, bf16* __restrict__ ygl)
{
    const int t = threadIdx.x;
    const int dl = t >> 4, s = t & 15;
    const int d = blockIdx.x * 32 + dl;
    const int c = blockIdx.y;
    const float A = -__expf(Alog[d * DS + s]);
    const float Dv = Dskip[d];
    const int l0 = c * CLEN;
    const float* pdt = dt  + (size_t)l0 * DI + d;
    const float* pu  = u   + (size_t)l0 * DI + d;
    const float* pB  = dbc + (size_t)l0 * NXPAD + DTR + s;
    const float* pC  = dbc + (size_t)l0 * NXPAD + DTR + DS + s;
    float h = hin[(size_t)c * (DI * DS) + d * DS + s];
#pragma unroll 2
    for (int i = 0; i < CLEN; i++) {
        const float dtv = pdt[i * DI];
        const float uv  = pu [i * DI];
        const float Bv  = pB [i * NXPAD];
        const float Cv  = pC [i * NXPAD];
        const float a = __expf(A * dtv);
        const float b = dtv * Bv * uv;
        h = a * h + b;
        float p = h * Cv;
        p += __shfl_xor_sync(0xffffffffu, p, 8);
        p += __shfl_xor_sync(0xffffffffu, p, 4);
        p += __shfl_xor_sync(0xffffffffu, p, 2);
        p += __shfl_xor_sync(0xffffffffu, p, 1);
        if (s == 0) {
            const int l = l0 + i;
            const float zv  = xz[(size_t)l * (2 * DI) + DI + d];
            const float sig = 1.f / (1.f + __expf(-zv));
            const float v = (p + uv * Dv) * (zv * sig);
            bf16 hh, ll;
            split_bf(v, hh, ll);
            ygh[(size_t)l * DI + d] = hh;
            ygl[(size_t)l * DI + d] = ll;
        }
    }
}

// ---------------- host ----------------
template<typename T>
static T* symaddr(const void* sym)
{
    void* p = nullptr;
    cudaGetSymbolAddress(&p, sym);
    return (T*)p;
}

extern "C" void kernel_launch(void* const* d_in, const int* in_sizes, int n_in,
                              void* d_out, int out_size)
{
    const float* x     = (const float*)d_in[0];
    const float* adj   = (const float*)d_in[1];
    const float* gcn_w = (const float*)d_in[2];
    const float* gcn_b = (const float*)d_in[3];
    const float* ln_g  = (const float*)d_in[4];
    const float* ln_b  = (const float*)d_in[5];
    const float* w_in  = (const float*)d_in[6];
    const float* conv_w= (const float*)d_in[7];
    const float* conv_b= (const float*)d_in[8];
    const float* w_xp  = (const float*)d_in[9];
    const float* w_dt  = (const float*)d_in[10];
    const float* b_dt  = (const float*)d_in[11];
    const float* A_log = (const float*)d_in[12];
    const float* D_skip= (const float*)d_in[13];
    const float* w_out = (const float*)d_in[14];
    float* out = (float*)d_out;

    float* part = symaddr<float>(g_part);
    float* h1   = symaddr<float>(g_h1);
    float* xz   = symaddr<float>(g_xz);
    float* u    = symaddr<float>(g_u);
    float* wxpp = symaddr<float>(g_wxpp);
    float* dbc  = symaddr<float>(g_dbc);
    float* dt   = symaddr<float>(g_dt);
    float* cP   = symaddr<float>(g_cP);
    float* cS   = symaddr<float>(g_cS);
    float* hin  = symaddr<float>(g_hin);

    bf16* adjh = symaddr<bf16>(g_adjh); bf16* adjl = symaddr<bf16>(g_adjl);
    bf16* t0h  = symaddr<bf16>(g_t0h);  bf16* t0l  = symaddr<bf16>(g_t0l);
    bf16* hlnh = symaddr<bf16>(g_hlnh); bf16* hlnl = symaddr<bf16>(g_hlnl);
    bf16* uh   = symaddr<bf16>(g_uh);   bf16* ul   = symaddr<bf16>(g_ul);
    bf16* ygh  = symaddr<bf16>(g_ygh);  bf16* ygl  = symaddr<bf16>(g_ygl);
    uint32_t* xph = symaddr<uint32_t>(g_xph); uint32_t* xpl = symaddr<uint32_t>(g_xpl);
    uint32_t* gwh = symaddr<uint32_t>(g_gwh); uint32_t* gwl = symaddr<uint32_t>(g_gwl);
    uint32_t* wih = symaddr<uint32_t>(g_wih); uint32_t* wil = symaddr<uint32_t>(g_wil);
    uint32_t* wxh = symaddr<uint32_t>(g_wxh); uint32_t* wxl = symaddr<uint32_t>(g_wxl);
    uint32_t* woh = symaddr<uint32_t>(g_woh); uint32_t* wol = symaddr<uint32_t>(g_wol);

    cudaFuncSetAttribute(mma_gemm, cudaFuncAttributeMaxDynamicSharedMemorySize, MMA_SMEM);

    // ---- converters (static operands) ----
    cvtA_k<<<(LSEQ * LSEQ) / 1024, 256>>>(adj, adjh, adjl);
    cvtB_k<<<(LSEQ / 2 * DM) / 1024, 256>>>(x, xph, xpl, DM);
    cvtB_k<<<(DM / 2 * DM) / 1024, 256>>>(gcn_w, gwh, gwl, DM);
    cvtB_k<<<(DM / 2 * 2 * DI) / 1024, 256>>>(w_in, wih, wil, 2 * DI);
    padw_k<<<(DI * NXPAD) / 256, 256>>>(w_xp, wxpp);
    cvtB_k<<<(DI / 2 * NXPAD) / 1024, 256>>>(wxpp, wxh, wxl, NXPAD);
    cvtB_k<<<(DI / 2 * DM) / 1024, 256>>>(w_out, woh, wol, DM);

    // 1) adj @ x, split-K=8 -> grid 1024
    mma_gemm<<<dim3(DM / BN, LSEQ / BM, 8), 256, MMA_SMEM>>>(
        adjh, adjl, xph, xpl, part, LSEQ / 8, DM, LSEQ, (size_t)LSEQ * DM);
    reduce_bf_k<<<(LSEQ * DM) / 1024, 256>>>(part, t0h, t0l, (size_t)LSEQ * DM, 8);

    // 2) h1 = relu(t0 @ gcn_w + b), split-K=2 -> grid 256
    mma_gemm<<<dim3(DM / BN, LSEQ / BM, 2), 256, MMA_SMEM>>>(
        t0h, t0l, gwh, gwl, part, DM / 2, DM, DM, (size_t)LSEQ * DM);
    gcnfin_k<<<(LSEQ * DM) / 1024, 256>>>(part, gcn_b, h1);

    // 3) layernorm -> hln hi/lo
    ln_k<<<LSEQ, 256>>>(h1, ln_g, ln_b, hlnh, hlnl);
    // 4) xz = hln @ w_in -> grid 512
    mma_gemm<<<dim3((2 * DI) / BN, LSEQ / BM), 256, MMA_SMEM>>>(
        hlnh, hlnl, wih, wil, xz, DM, 2 * DI, DM, 0);
    // 5) u = silu(conv(xc) + b) -> fp32 + hi/lo
    conv_silu_k<<<(LSEQ * DI) / 256, 256>>>(xz, conv_w, conv_b, u, uh, ul);
    // 6) dbc = u @ w_xp, split-K=8 -> grid 256
    mma_gemm<<<dim3(NXPAD / BN, LSEQ / BM, 8), 256, MMA_SMEM>>>(
        uh, ul, wxh, wxl, part, DI / 8, NXPAD, DI, (size_t)LSEQ * NXPAD);
    reduce_k<<<(LSEQ * NXPAD) / 1024, 256>>>(part, dbc, (size_t)LSEQ * NXPAD, 8);
    // 7) dt
    dt_k<<<(LSEQ * DI) / 256, 256>>>(dbc, w_dt, b_dt, dt);
    // 8-10) chunked selective scan
    scan1_k<<<dim3(DI / 32, NC), 512>>>(dt, u, dbc, A_log, cP, cS);
    scan2_k<<<(DI * DS) / 512, 512>>>(cP, cS, hin);
    scan3_k<<<dim3(DI / 32, NC), 512>>>(dt, u, dbc, A_log, hin, xz, D_skip, ygh, ygl);
    // 11) out = yg @ w_out, split-K=4 -> grid 512
    mma_gemm<<<dim3(DM / BN, LSEQ / BM, 4), 256, MMA_SMEM>>>(
        ygh, ygl, woh, wol, part, DI / 4, DM, DI, (size_t)LSEQ * DM);
    reduce_k<<<(LSEQ * DM) / 1024, 256>>>(part, out, (size_t)LSEQ * DM, 4);
}

// round 9
// speedup vs baseline: 1.0643x; 1.0643x over previous
#include <cuda_runtime.h>
#include <cuda_bf16.h>
#include <cstdint>
#include <math.h>

// ---------------- problem constants ----------------
#define LSEQ   4096
#define DM     256
#define DI     512
#define DS     16
#define DTR    16
#define NXP    48
#define NXPAD  128          // dbc row stride (padded to BN)
#define DCONV  4
#define NC     64
#define CLEN   64
#define LN_EPS 1e-5f

typedef __nv_bfloat16 bf16;

// ---------------- device scratch ----------------
__device__ float g_part[8*LSEQ*DM];        // split-K partials (32 MB)
__device__ float g_hln [LSEQ*DM];
__device__ float g_t0  [LSEQ*DM];
__device__ float g_xz  [LSEQ*2*DI];
__device__ float g_u   [LSEQ*DI];
__device__ float g_wxpp[DI*NXPAD];
__device__ float g_dbc [LSEQ*NXPAD];
__device__ float g_dt  [LSEQ*DI];
__device__ float g_cP  [NC*DI*DS];
__device__ float g_cS  [NC*DI*DS];
__device__ float g_hin [NC*DI*DS];
__device__ float g_yg  [LSEQ*DI];

// ================= helpers =================
__device__ __forceinline__ uint32_t smem_u32(const void* p) {
    uint32_t a;
    asm("{ .reg .u64 t; cvta.to.shared.u64 t, %1; cvt.u32.u64 %0, t; }" : "=r"(a) : "l"(p));
    return a;
}

#define LDMATRIX_X4(r, addr) \
    asm volatile("ldmatrix.sync.aligned.m8n8.x4.shared.b16 {%0,%1,%2,%3}, [%4];" \
        : "=r"((r)[0]), "=r"((r)[1]), "=r"((r)[2]), "=r"((r)[3]) : "r"(addr))

#define MMA_BF16(c, a, b) \
    asm volatile("mma.sync.aligned.m16n8k16.row.col.f32.bf16.bf16.f32 " \
        "{%0,%1,%2,%3},{%4,%5,%6,%7},{%8,%9},{%0,%1,%2,%3};" \
        : "+f"((c)[0]), "+f"((c)[1]), "+f"((c)[2]), "+f"((c)[3]) \
        : "r"((a)[0]), "r"((a)[1]), "r"((a)[2]), "r"((a)[3]), "r"((b)[0]), "r"((b)[1]))

__device__ __forceinline__ uint32_t pack2(float e0, float e1) {
    __nv_bfloat162 v = __floats2bfloat162_rn(e0, e1);   // .x = e0 (low 16)
    return *(uint32_t*)&v;
}
__device__ __forceinline__ void split1(float v, float& hi, float& lo) {
    bf16 h = __float2bfloat16_rn(v);
    hi = __bfloat162float(h);
    lo = v - hi;
}

// ================= bf16x3-split GEMM, 128x128 tile, 16 warps =================
// C = Ahi*Bhi + Ahi*Blo + Alo*Bhi. BK=32, warp grid 4M x 4N, warp tile 32x32.
// Double-buffered SMEM, one __syncthreads per chunk, register-staged loads,
// bf16 split done once per CTA at stage time.
#define BM 128
#define BN 128
#define BK 32
#define NTHR 512
#define ASTR   40                            // bf16 per A smem row (80 B)
#define BSTRW  136                           // u32 words per B k2-row (544 B)
#define A_LO_OFF (BM*ASTR*2)                 // 10240
#define B_HI_OFF (2*BM*ASTR*2)               // 20480
#define B_LO_OFF (B_HI_OFF + 16*BSTRW*4)     // 29184
#define STAGE_B  (B_LO_OFF + 16*BSTRW*4)     // 37888
#define MMA_SMEM (2*STAGE_B)                 // 75776

__global__ __launch_bounds__(NTHR)
void mma_gemm(const float* __restrict__ A, const float* __restrict__ B,
              float* __restrict__ C, int K, int Ng, int lda, size_t csplit)
{
    extern __shared__ char smem[];
    const uint32_t sb = smem_u32(smem);
    const int tid  = threadIdx.x;
    const int wid  = tid >> 5, lane = tid & 31;
    const int warpM = wid & 3, warpN = wid >> 2;
    const int m0 = blockIdx.y * BM;
    const int n0 = blockIdx.x * BN;
    const int z  = blockIdx.z;
    const int g  = lane >> 2, tg = lane & 3;

    const float* Az = A + (size_t)z * K;
    const float* Bz = B + (size_t)z * K * Ng;
    float*       Cz = C + (size_t)z * csplit;
    const int nch = K / BK;

    // staging indices
    const int ar  = tid >> 2;            // A row 0..127
    const int as8 = (tid & 3) * 8;       // A k-seg (8 floats)
    const int br  = tid >> 5;            // B k2-row 0..15
    const int bc4 = (tid & 31) * 4;      // B n cols (4)

    float4 ga[2], gb0, gb1;
    auto ldG = [&](int c) {
        const int k0 = c * BK;
        const float* arow = Az + (size_t)(m0 + ar) * lda + k0 + as8;
        ga[0] = *(const float4*)(arow);
        ga[1] = *(const float4*)(arow + 4);
        gb0 = *(const float4*)(Bz + (size_t)(k0 + 2 * br)     * Ng + n0 + bc4);
        gb1 = *(const float4*)(Bz + (size_t)(k0 + 2 * br + 1) * Ng + n0 + bc4);
    };

    auto stS = [&](int s) {
        char* base = smem + s * STAGE_B;
#pragma unroll
        for (int j = 0; j < 2; j++) {
            const float* e = &ga[j].x;
            float h[4], l[4];
#pragma unroll
            for (int q = 0; q < 4; q++) split1(e[q], h[q], l[q]);
            const uint32_t off = (uint32_t)(ar * ASTR + as8 + 4 * j) * 2;
            *(uint2*)(base + off)            = make_uint2(pack2(h[0], h[1]), pack2(h[2], h[3]));
            *(uint2*)(base + A_LO_OFF + off) = make_uint2(pack2(l[0], l[1]), pack2(l[2], l[3]));
        }
        const float* e0 = &gb0.x;
        const float* e1 = &gb1.x;
        uint32_t* bh = (uint32_t*)(base + B_HI_OFF);
        uint32_t* bl = (uint32_t*)(base + B_LO_OFF);
#pragma unroll
        for (int j = 0; j < 4; j++) {
            float h0, l0, h1, l1;
            split1(e0[j], h0, l0);
            split1(e1[j], h1, l1);
            bh[br * BSTRW + bc4 + j] = pack2(h0, h1);   // {k even, k odd}
            bl[br * BSTRW + bc4 + j] = pack2(l0, l1);
        }
    };

    float c[2][4][4];
#pragma unroll
    for (int mt = 0; mt < 2; mt++)
#pragma unroll
        for (int nt = 0; nt < 4; nt++)
#pragma unroll
            for (int i = 0; i < 4; i++) c[mt][nt][i] = 0.f;

    const uint32_t aHiOff = (uint32_t)((warpM * 32 + (lane & 15)) * ASTR + (lane >> 4) * 8) * 2;

    ldG(0);
    stS(0);
    __syncthreads();

    for (int ch = 0; ch < nch; ch++) {
        const int st = ch & 1;
        if (ch + 1 < nch) ldG(ch + 1);

        const char* base = smem + st * STAGE_B;
        const uint32_t aB = sb + st * STAGE_B + aHiOff;
        const uint32_t* bh = (const uint32_t*)(base + B_HI_OFF);
        const uint32_t* bl = (const uint32_t*)(base + B_LO_OFF);
#pragma unroll
        for (int kh = 0; kh < 2; kh++) {
            uint32_t bhi[4][2], blo[4][2];
#pragma unroll
            for (int nt = 0; nt < 4; nt++) {
                const int w = (kh * 8 + tg) * BSTRW + warpN * 32 + nt * 8 + g;
                bhi[nt][0] = bh[w];  bhi[nt][1] = bh[w + 4 * BSTRW];
                blo[nt][0] = bl[w];  blo[nt][1] = bl[w + 4 * BSTRW];
            }
#pragma unroll
            for (int mt = 0; mt < 2; mt++) {
                uint32_t ah[4], al[4];
                const uint32_t off = (uint32_t)(mt * 16 * ASTR + kh * 16) * 2;
                LDMATRIX_X4(ah, aB + off);
                LDMATRIX_X4(al, aB + A_LO_OFF + off);
#pragma unroll
                for (int nt = 0; nt < 4; nt++) {
                    MMA_BF16(c[mt][nt], ah, bhi[nt]);
                    MMA_BF16(c[mt][nt], ah, blo[nt]);
                    MMA_BF16(c[mt][nt], al, bhi[nt]);
                }
            }
        }
        if (ch + 1 < nch) stS(st ^ 1);   // safe: drained at barrier ending ch-1
        __syncthreads();
    }

    // ---- epilogue ----
#pragma unroll
    for (int mt = 0; mt < 2; mt++)
#pragma unroll
        for (int nt = 0; nt < 4; nt++) {
            const int row = m0 + warpM * 32 + mt * 16 + g;
            const int col = n0 + warpN * 32 + nt * 8 + 2 * tg;
            *(float2*)(Cz + (size_t)row * Ng + col)       = make_float2(c[mt][nt][0], c[mt][nt][1]);
            *(float2*)(Cz + (size_t)(row + 8) * Ng + col) = make_float2(c[mt][nt][2], c[mt][nt][3]);
        }
}

// ---------------- split-K reduction ----------------
__global__ __launch_bounds__(256)
void reduce_k(const float* __restrict__ p, float* __restrict__ out,
              size_t stride, int count)
{
    const size_t i = ((size_t)blockIdx.x * 256 + threadIdx.x) * 4;
    float4 s = *(const float4*)(p + i);
    for (int cc = 1; cc < count; cc++) {
        float4 v = *(const float4*)(p + cc * stride + i);
        s.x += v.x; s.y += v.y; s.z += v.z; s.w += v.w;
    }
    *(float4*)(out + i) = s;
}

// ---------------- pad w_xp 512x48 -> 512x128 ----------------
__global__ __launch_bounds__(256)
void padw_k(const float* __restrict__ wxp, float* __restrict__ wxpp)
{
    const int i = blockIdx.x * 256 + threadIdx.x;   // over DI*NXPAD
    const int r = i >> 7, col = i & 127;
    wxpp[i] = (col < NXP) ? wxp[r * NXP + col] : 0.f;
}

// ---------------- layernorm fused with gcn finish ----------------
// v = relu(sum_{c<4} part[c][row,tid] + gcn_b[tid]); then LN.
__global__ __launch_bounds__(256)
void ln_k(const float* __restrict__ part, const float* __restrict__ gb,
          const float* __restrict__ g, const float* __restrict__ b,
          float* __restrict__ out)
{
    const int row = blockIdx.x;
    const int tid = threadIdx.x;
    const size_t idx = (size_t)row * DM + tid;
    float v = part[idx] + part[idx + (size_t)LSEQ * DM]
            + part[idx + 2 * (size_t)LSEQ * DM] + part[idx + 3 * (size_t)LSEQ * DM]
            + gb[tid];
    v = fmaxf(v, 0.f);
    float s = v, s2 = v * v;
#pragma unroll
    for (int o = 16; o; o >>= 1) {
        s  += __shfl_xor_sync(0xffffffffu, s,  o);
        s2 += __shfl_xor_sync(0xffffffffu, s2, o);
    }
    __shared__ float ws[8], ws2[8];
    if ((tid & 31) == 0) { ws[tid >> 5] = s; ws2[tid >> 5] = s2; }
    __syncthreads();
    float ts = 0.f, ts2 = 0.f;
#pragma unroll
    for (int i = 0; i < 8; i++) { ts += ws[i]; ts2 += ws2[i]; }
    const float mu  = ts * (1.f / DM);
    const float var = ts2 * (1.f / DM) - mu * mu;
    const float r   = rsqrtf(var + LN_EPS);
    out[idx] = (v - mu) * r * g[tid] + b[tid];
}

// ---------------- conv + silu ----------------
__global__ __launch_bounds__(256)
void conv_silu_k(const float* __restrict__ xz, const float* __restrict__ cw,
                 const float* __restrict__ cb, float* __restrict__ u)
{
    const int idx = blockIdx.x * 256 + threadIdx.x;
    const int l = idx >> 9, d = idx & (DI - 1);
    float s = cb[d];
#pragma unroll
    for (int k = 0; k < DCONV; k++) {
        const int ls = l - (DCONV - 1) + k;
        if (ls >= 0) s += xz[(size_t)ls * (2 * DI) + d] * cw[d * DCONV + k];
    }
    const float sig = 1.f / (1.f + __expf(-s));
    u[idx] = s * sig;
}

// ---------------- dt ----------------
__global__ __launch_bounds__(256)
void dt_k(const float* __restrict__ dbc, const float* __restrict__ wdt,
          const float* __restrict__ bdt, float* __restrict__ dt)
{
    const int idx = blockIdx.x * 256 + threadIdx.x;
    const int l = idx >> 9, d = idx & (DI - 1);
    float s = bdt[d];
    const float* dr = dbc + (size_t)l * NXPAD;
#pragma unroll
    for (int k = 0; k < DTR; k++) s += dr[k] * wdt[k * DI + d];
    dt[idx] = (s > 20.f) ? s : log1pf(__expf(s));
}

// ---------------- scan phase 1 ----------------
__global__ __launch_bounds__(512)
void scan1_k(const float* __restrict__ dt, const float* __restrict__ u,
             const float* __restrict__ dbc, const float* __restrict__ Alog,
             float* __restrict__ cP, float* __restrict__ cS)
{
    const int t = threadIdx.x;
    const int dl = t >> 4, s = t & 15;
    const int d = blockIdx.x * 32 + dl;
    const int c = blockIdx.y;
    const float A = -__expf(Alog[d * DS + s]);
    const int l0 = c * CLEN;
    const float* pdt = dt  + (size_t)l0 * DI + d;
    const float* pu  = u   + (size_t)l0 * DI + d;
    const float* pB  = dbc + (size_t)l0 * NXPAD + DTR + s;
    float P = 1.f, S = 0.f;
#pragma unroll 4
    for (int i = 0; i < CLEN; i++) {
        const float dtv = pdt[i * DI];
        const float uv  = pu [i * DI];
        const float Bv  = pB [i * NXPAD];
        const float a = __expf(A * dtv);
        const float b = dtv * Bv * uv;
        P *= a;
        S = a * S + b;
    }
    const int idx = d * DS + s;
    cP[(size_t)c * (DI * DS) + idx] = P;
    cS[(size_t)c * (DI * DS) + idx] = S;
}

// ---------------- scan phase 2 ----------------
__global__ __launch_bounds__(512)
void scan2_k(const float* __restrict__ cP, const float* __restrict__ cS,
             float* __restrict__ hin)
{
    const int idx = blockIdx.x * 512 + threadIdx.x;
    float h = 0.f;
#pragma unroll 4
    for (int c = 0; c < NC; c++) {
        hin[(size_t)c * (DI * DS) + idx] = h;
        h = cP[(size_t)c * (DI * DS) + idx] * h + cS[(size_t)c * (DI * DS) + idx];
    }
}

// ---------------- scan phase 3 ----------------
__global__ __launch_bounds__(512)
void scan3_k(const float* __restrict__ dt, const float* __restrict__ u,
             const float* __restrict__ dbc, const float* __restrict__ Alog,
             const float* __restrict__ hin, const float* __restrict__ xz,
             const float* __restrict__ Dskip, float* __restrict__ yg)
{
    const int t = threadIdx.x;
    const int dl = t >> 4, s = t & 15;
    const int d = blockIdx.x * 32 + dl;
    const int c = blockIdx.y;
    const float A = -__expf(Alog[d * DS + s]);
    const float Dv = Dskip[d];
    const int l0 = c * CLEN;
    const float* pdt = dt  + (size_t)l0 * DI + d;
    const float* pu  = u   + (size_t)l0 * DI + d;
    const float* pB  = dbc + (size_t)l0 * NXPAD + DTR + s;
    const float* pC  = dbc + (size_t)l0 * NXPAD + DTR + DS + s;
    float h = hin[(size_t)c * (DI * DS) + d * DS + s];
#pragma unroll 2
    for (int i = 0; i < CLEN; i++) {
        const float dtv = pdt[i * DI];
        const float uv  = pu [i * DI];
        const float Bv  = pB [i * NXPAD];
        const float Cv  = pC [i * NXPAD];
        const float a = __expf(A * dtv);
        const float b = dtv * Bv * uv;
        h = a * h + b;
        float p = h * Cv;
        p += __shfl_xor_sync(0xffffffffu, p, 8);
        p += __shfl_xor_sync(0xffffffffu, p, 4);
        p += __shfl_xor_sync(0xffffffffu, p, 2);
        p += __shfl_xor_sync(0xffffffffu, p, 1);
        if (s == 0) {
            const int l = l0 + i;
            const float zv  = xz[(size_t)l * (2 * DI) + DI + d];
            const float sig = 1.f / (1.f + __expf(-zv));
            yg[(size_t)l * DI + d] = (p + uv * Dv) * (zv * sig);
        }
    }
}

// ---------------- host ----------------
static float* symaddr(const void* sym)
{
    void* p = nullptr;
    cudaGetSymbolAddress(&p, sym);
    return (float*)p;
}

extern "C" void kernel_launch(void* const* d_in, const int* in_sizes, int n_in,
                              void* d_out, int out_size)
{
    const float* x     = (const float*)d_in[0];
    const float* adj   = (const float*)d_in[1];
    const float* gcn_w = (const float*)d_in[2];
    const float* gcn_b = (const float*)d_in[3];
    const float* ln_g  = (const float*)d_in[4];
    const float* ln_b  = (const float*)d_in[5];
    const float* w_in  = (const float*)d_in[6];
    const float* conv_w= (const float*)d_in[7];
    const float* conv_b= (const float*)d_in[8];
    const float* w_xp  = (const float*)d_in[9];
    const float* w_dt  = (const float*)d_in[10];
    const float* b_dt  = (const float*)d_in[11];
    const float* A_log = (const float*)d_in[12];
    const float* D_skip= (const float*)d_in[13];
    const float* w_out = (const float*)d_in[14];
    float* out = (float*)d_out;

    float* part = symaddr(g_part);
    float* hln  = symaddr(g_hln);
    float* t0   = symaddr(g_t0);
    float* xz   = symaddr(g_xz);
    float* u    = symaddr(g_u);
    float* wxpp = symaddr(g_wxpp);
    float* dbc  = symaddr(g_dbc);
    float* dt   = symaddr(g_dt);
    float* cP   = symaddr(g_cP);
    float* cS   = symaddr(g_cS);
    float* hin  = symaddr(g_hin);
    float* yg   = symaddr(g_yg);

    cudaFuncSetAttribute(mma_gemm, cudaFuncAttributeMaxDynamicSharedMemorySize, MMA_SMEM);

    // 0) pad w_xp to N=128
    padw_k<<<(DI * NXPAD) / 256, 256>>>(w_xp, wxpp);

    // 1) adj @ x, split-K=8 [K=512 each] -> grid (2,32,8) = 512 CTAs
    mma_gemm<<<dim3(DM / BN, LSEQ / BM, 8), NTHR, MMA_SMEM>>>(
        adj, x, part, LSEQ / 8, DM, LSEQ, (size_t)LSEQ * DM);
    reduce_k<<<(LSEQ * DM) / 1024, 256>>>(part, t0, (size_t)LSEQ * DM, 8);

    // 2) t0 @ gcn_w, split-K=4 [K=64 each] -> grid (2,32,4) = 256 CTAs
    mma_gemm<<<dim3(DM / BN, LSEQ / BM, 4), NTHR, MMA_SMEM>>>(
        t0, gcn_w, part, DM / 4, DM, DM, (size_t)LSEQ * DM);
    // 3) layernorm (fused: 4-partial sum + bias + relu + LN)
    ln_k<<<LSEQ, 256>>>(part, gcn_b, ln_g, ln_b, hln);

    // 4) xz = hln @ w_in -> grid (8,32) = 256 CTAs
    mma_gemm<<<dim3((2 * DI) / BN, LSEQ / BM, 1), NTHR, MMA_SMEM>>>(
        hln, w_in, xz, DM, 2 * DI, DM, 0);
    // 5) u = silu(conv(xc) + b)
    conv_silu_k<<<(LSEQ * DI) / 256, 256>>>(xz, conv_w, conv_b, u);

    // 6) dbc = u @ w_xp (N=128 padded), split-K=8 [K=64 each] -> grid (1,32,8) = 256 CTAs
    mma_gemm<<<dim3(NXPAD / BN, LSEQ / BM, 8), NTHR, MMA_SMEM>>>(
        u, wxpp, part, DI / 8, NXPAD, DI, (size_t)LSEQ * NXPAD);
    reduce_k<<<(LSEQ * NXPAD) / 1024, 256>>>(part, dbc, (size_t)LSEQ * NXPAD, 8);

    // 7) dt
    dt_k<<<(LSEQ * DI) / 256, 256>>>(dbc, w_dt, b_dt, dt);
    // 8-10) chunked selective scan
    scan1_k<<<dim3(DI / 32, NC), 512>>>(dt, u, dbc, A_log, cP, cS);
    scan2_k<<<(DI * DS) / 512, 512>>>(cP, cS, hin);
    scan3_k<<<dim3(DI / 32, NC), 512>>>(dt, u, dbc, A_log, hin, xz, D_skip, yg);

    // 11) out = yg @ w_out, split-K=4 [K=128 each] -> grid (2,32,4) = 256 CTAs
    mma_gemm<<<dim3(DM / BN, LSEQ / BM, 4), NTHR, MMA_SMEM>>>(
        yg, w_out, part, DI / 4, DM, DI, (size_t)LSEQ * DM);
    reduce_k<<<(LSEQ * DM) / 1024, 256>>>(part, out, (size_t)LSEQ * DM, 4);
}

// round 10
// speedup vs baseline: 1.2085x; 1.1354x over previous
#include <cuda_runtime.h>
#include <cuda_fp16.h>
#include <cstdint>
#include <math.h>

// ---------------- problem constants ----------------
#define LSEQ   4096
#define DM     256
#define DI     512
#define DS     16
#define DTR    16
#define NXP    48
#define NXPAD  128
#define DCONV  4
#define NC     64
#define CLEN   64
#define LN_EPS 1e-5f

// ---------------- device scratch ----------------
__device__ float g_part[8*LSEQ*DM];
__device__ float g_hln [LSEQ*DM];
__device__ float g_t0  [LSEQ*DM];
__device__ float g_xz  [LSEQ*2*DI];
__device__ float g_u   [LSEQ*DI];
__device__ float g_wxpp[DI*NXPAD];
__device__ float g_dbc [LSEQ*NXPAD];
__device__ float g_dt  [LSEQ*DI];
__device__ float g_cP  [NC*DI*DS];
__device__ float g_cS  [NC*DI*DS];
__device__ float g_hin [NC*DI*DS];
__device__ float g_yg  [LSEQ*DI];

// ================= helpers =================
__device__ __forceinline__ uint32_t smem_u32(const void* p) {
    uint32_t a;
    asm("{ .reg .u64 t; cvta.to.shared.u64 t, %1; cvt.u32.u64 %0, t; }" : "=r"(a) : "l"(p));
    return a;
}

#define LDMATRIX_X4(r, addr) \
    asm volatile("ldmatrix.sync.aligned.m8n8.x4.shared.b16 {%0,%1,%2,%3}, [%4];" \
        : "=r"((r)[0]), "=r"((r)[1]), "=r"((r)[2]), "=r"((r)[3]) : "r"(addr))

#define MMA_F16(c, a, b) \
    asm volatile("mma.sync.aligned.m16n8k16.row.col.f32.f16.f16.f32 " \
        "{%0,%1,%2,%3},{%4,%5,%6,%7},{%8,%9},{%0,%1,%2,%3};" \
        : "+f"((c)[0]), "+f"((c)[1]), "+f"((c)[2]), "+f"((c)[3]) \
        : "r"((a)[0]), "r"((a)[1]), "r"((a)[2]), "r"((a)[3]), "r"((b)[0]), "r"((b)[1]))

__device__ __forceinline__ uint32_t pack2h(float e0, float e1) {
    __half2 v = __floats2half2_rn(e0, e1);   // .x = e0 (low 16)
    return *(uint32_t*)&v;
}
__device__ __forceinline__ void split1h(float v, float& hi, float& lo) {
    __half h = __float2half_rn(v);
    hi = __half2float(h);
    lo = v - hi;
}

// ================= fp16x2-split GEMM, 128x128 tile, 16 warps =================
// C = (Ahi + Alo) * fp16(B)  — A exact via fp16 hi/lo pair, B single fp16.
// BK=32, warp grid 4M x 4N, warp tile 32x32. Double-buffered SMEM, one
// __syncthreads per chunk, register-staged global loads, split at stage time.
#define BM 128
#define BN 128
#define BK 32
#define NTHR 512
#define ASTR   40                            // fp16 per A smem row (80 B)
#define BSTRW  136                           // u32 words per B k2-row (544 B)
#define A_LO_OFF (BM*ASTR*2)                 // 10240
#define B_OFF    (2*BM*ASTR*2)               // 20480
#define STAGE_B  (B_OFF + 16*BSTRW*4)        // 29184
#define MMA_SMEM (2*STAGE_B)                 // 58368

__global__ __launch_bounds__(NTHR)
void mma_gemm(const float* __restrict__ A, const float* __restrict__ B,
              float* __restrict__ C, int K, int Ng, int lda, size_t csplit)
{
    extern __shared__ char smem[];
    const uint32_t sb = smem_u32(smem);
    const int tid  = threadIdx.x;
    const int wid  = tid >> 5, lane = tid & 31;
    const int warpM = wid & 3, warpN = wid >> 2;
    const int m0 = blockIdx.y * BM;
    const int n0 = blockIdx.x * BN;
    const int z  = blockIdx.z;
    const int g  = lane >> 2, tg = lane & 3;

    const float* Az = A + (size_t)z * K;
    const float* Bz = B + (size_t)z * K * Ng;
    float*       Cz = C + (size_t)z * csplit;
    const int nch = K / BK;

    // staging indices
    const int ar  = tid >> 2;            // A row 0..127
    const int as8 = (tid & 3) * 8;       // A k-seg (8 floats)
    const int br  = tid >> 5;            // B k2-row 0..15
    const int bc4 = (tid & 31) * 4;      // B word cols (4)

    float4 ga[2], gb0, gb1;
    auto ldG = [&](int c) {
        const int k0 = c * BK;
        const float* arow = Az + (size_t)(m0 + ar) * lda + k0 + as8;
        ga[0] = *(const float4*)(arow);
        ga[1] = *(const float4*)(arow + 4);
        gb0 = *(const float4*)(Bz + (size_t)(k0 + 2 * br)     * Ng + n0 + bc4);
        gb1 = *(const float4*)(Bz + (size_t)(k0 + 2 * br + 1) * Ng + n0 + bc4);
    };

    auto stS = [&](int s) {
        char* base = smem + s * STAGE_B;
#pragma unroll
        for (int j = 0; j < 2; j++) {
            const float* e = &ga[j].x;
            float h[4], l[4];
#pragma unroll
            for (int q = 0; q < 4; q++) split1h(e[q], h[q], l[q]);
            const uint32_t off = (uint32_t)(ar * ASTR + as8 + 4 * j) * 2;
            *(uint2*)(base + off)            = make_uint2(pack2h(h[0], h[1]), pack2h(h[2], h[3]));
            *(uint2*)(base + A_LO_OFF + off) = make_uint2(pack2h(l[0], l[1]), pack2h(l[2], l[3]));
        }
        const float* e0 = &gb0.x;
        const float* e1 = &gb1.x;
        uint32_t* bh = (uint32_t*)(base + B_OFF);
        uint32_t w4[4];
#pragma unroll
        for (int j = 0; j < 4; j++) w4[j] = pack2h(e0[j], e1[j]);   // {k even, k odd}
        *(uint4*)(bh + br * BSTRW + bc4) = make_uint4(w4[0], w4[1], w4[2], w4[3]);
    };

    float c[2][4][4];
#pragma unroll
    for (int mt = 0; mt < 2; mt++)
#pragma unroll
        for (int nt = 0; nt < 4; nt++)
#pragma unroll
            for (int i = 0; i < 4; i++) c[mt][nt][i] = 0.f;

    const uint32_t aHiOff = (uint32_t)((warpM * 32 + (lane & 15)) * ASTR + (lane >> 4) * 8) * 2;

    ldG(0);
    stS(0);
    __syncthreads();

    for (int ch = 0; ch < nch; ch++) {
        const int st = ch & 1;
        if (ch + 1 < nch) ldG(ch + 1);

        const char* base = smem + st * STAGE_B;
        const uint32_t aB = sb + st * STAGE_B + aHiOff;
        const uint32_t* bh = (const uint32_t*)(base + B_OFF);
#pragma unroll
        for (int kh = 0; kh < 2; kh++) {
            uint32_t bf[4][2];
#pragma unroll
            for (int nt = 0; nt < 4; nt++) {
                const int w = (kh * 8 + tg) * BSTRW + warpN * 32 + nt * 8 + g;
                bf[nt][0] = bh[w];
                bf[nt][1] = bh[w + 4 * BSTRW];
            }
#pragma unroll
            for (int mt = 0; mt < 2; mt++) {
                uint32_t ah[4], al[4];
                const uint32_t off = (uint32_t)(mt * 16 * ASTR + kh * 16) * 2;
                LDMATRIX_X4(ah, aB + off);
                LDMATRIX_X4(al, aB + A_LO_OFF + off);
#pragma unroll
                for (int nt = 0; nt < 4; nt++) {
                    MMA_F16(c[mt][nt], ah, bf[nt]);
                    MMA_F16(c[mt][nt], al, bf[nt]);
                }
            }
        }
        if (ch + 1 < nch) stS(st ^ 1);   // safe: drained at barrier ending ch-1
        __syncthreads();
    }

    // ---- epilogue ----
#pragma unroll
    for (int mt = 0; mt < 2; mt++)
#pragma unroll
        for (int nt = 0; nt < 4; nt++) {
            const int row = m0 + warpM * 32 + mt * 16 + g;
            const int col = n0 + warpN * 32 + nt * 8 + 2 * tg;
            *(float2*)(Cz + (size_t)row * Ng + col)       = make_float2(c[mt][nt][0], c[mt][nt][1]);
            *(float2*)(Cz + (size_t)(row + 8) * Ng + col) = make_float2(c[mt][nt][2], c[mt][nt][3]);
        }
}

// ---------------- split-K reduction ----------------
__global__ __launch_bounds__(256)
void reduce_k(const float* __restrict__ p, float* __restrict__ out,
              size_t stride, int count)
{
    const size_t i = ((size_t)blockIdx.x * 256 + threadIdx.x) * 4;
    float4 s = *(const float4*)(p + i);
    for (int cc = 1; cc < count; cc++) {
        float4 v = *(const float4*)(p + cc * stride + i);
        s.x += v.x; s.y += v.y; s.z += v.z; s.w += v.w;
    }
    *(float4*)(out + i) = s;
}

// ---------------- pad w_xp 512x48 -> 512x128 ----------------
__global__ __launch_bounds__(256)
void padw_k(const float* __restrict__ wxp, float* __restrict__ wxpp)
{
    const int i = blockIdx.x * 256 + threadIdx.x;
    const int r = i >> 7, col = i & 127;
    wxpp[i] = (col < NXP) ? wxp[r * NXP + col] : 0.f;
}

// ---------------- layernorm fused with gcn finish (4 partials + bias + relu) ----------------
__global__ __launch_bounds__(256)
void ln_k(const float* __restrict__ part, const float* __restrict__ gb,
          const float* __restrict__ g, const float* __restrict__ b,
          float* __restrict__ out)
{
    const int row = blockIdx.x;
    const int tid = threadIdx.x;
    const size_t idx = (size_t)row * DM + tid;
    float v = part[idx] + part[idx + (size_t)LSEQ * DM]
            + part[idx + 2 * (size_t)LSEQ * DM] + part[idx + 3 * (size_t)LSEQ * DM]
            + gb[tid];
    v = fmaxf(v, 0.f);
    float s = v, s2 = v * v;
#pragma unroll
    for (int o = 16; o; o >>= 1) {
        s  += __shfl_xor_sync(0xffffffffu, s,  o);
        s2 += __shfl_xor_sync(0xffffffffu, s2, o);
    }
    __shared__ float ws[8], ws2[8];
    if ((tid & 31) == 0) { ws[tid >> 5] = s; ws2[tid >> 5] = s2; }
    __syncthreads();
    float ts = 0.f, ts2 = 0.f;
#pragma unroll
    for (int i = 0; i < 8; i++) { ts += ws[i]; ts2 += ws2[i]; }
    const float mu  = ts * (1.f / DM);
    const float var = ts2 * (1.f / DM) - mu * mu;
    const float r   = rsqrtf(var + LN_EPS);
    out[idx] = (v - mu) * r * g[tid] + b[tid];
}

// ---------------- conv + silu ----------------
__global__ __launch_bounds__(256)
void conv_silu_k(const float* __restrict__ xz, const float* __restrict__ cw,
                 const float* __restrict__ cb, float* __restrict__ u)
{
    const int idx = blockIdx.x * 256 + threadIdx.x;
    const int l = idx >> 9, d = idx & (DI - 1);
    float s = cb[d];
#pragma unroll
    for (int k = 0; k < DCONV; k++) {
        const int ls = l - (DCONV - 1) + k;
        if (ls >= 0) s += xz[(size_t)ls * (2 * DI) + d] * cw[d * DCONV + k];
    }
    const float sig = 1.f / (1.f + __expf(-s));
    u[idx] = s * sig;
}

// ---------------- dt ----------------
__global__ __launch_bounds__(256)
void dt_k(const float* __restrict__ dbc, const float* __restrict__ wdt,
          const float* __restrict__ bdt, float* __restrict__ dt)
{
    const int idx = blockIdx.x * 256 + threadIdx.x;
    const int l = idx >> 9, d = idx & (DI - 1);
    float s = bdt[d];
    const float* dr = dbc + (size_t)l * NXPAD;
#pragma unroll
    for (int k = 0; k < DTR; k++) s += dr[k] * wdt[k * DI + d];
    dt[idx] = (s > 20.f) ? s : log1pf(__expf(s));
}

// ---------------- scan phase 1 ----------------
__global__ __launch_bounds__(512)
void scan1_k(const float* __restrict__ dt, const float* __restrict__ u,
             const float* __restrict__ dbc, const float* __restrict__ Alog,
             float* __restrict__ cP, float* __restrict__ cS)
{
    const int t = threadIdx.x;
    const int dl = t >> 4, s = t & 15;
    const int d = blockIdx.x * 32 + dl;
    const int c = blockIdx.y;
    const float A = -__expf(Alog[d * DS + s]);
    const int l0 = c * CLEN;
    const float* pdt = dt  + (size_t)l0 * DI + d;
    const float* pu  = u   + (size_t)l0 * DI + d;
    const float* pB  = dbc + (size_t)l0 * NXPAD + DTR + s;
    float P = 1.f, S = 0.f;
#pragma unroll 4
    for (int i = 0; i < CLEN; i++) {
        const float dtv = pdt[i * DI];
        const float uv  = pu [i * DI];
        const float Bv  = pB [i * NXPAD];
        const float a = __expf(A * dtv);
        const float b = dtv * Bv * uv;
        P *= a;
        S = a * S + b;
    }
    const int idx = d * DS + s;
    cP[(size_t)c * (DI * DS) + idx] = P;
    cS[(size_t)c * (DI * DS) + idx] = S;
}

// ---------------- scan phase 2 ----------------
__global__ __launch_bounds__(512)
void scan2_k(const float* __restrict__ cP, const float* __restrict__ cS,
             float* __restrict__ hin)
{
    const int idx = blockIdx.x * 512 + threadIdx.x;
    float h = 0.f;
#pragma unroll 4
    for (int c = 0; c < NC; c++) {
        hin[(size_t)c * (DI * DS) + idx] = h;
        h = cP[(size_t)c * (DI * DS) + idx] * h + cS[(size_t)c * (DI * DS) + idx];
    }
}

// ---------------- scan phase 3 ----------------
__global__ __launch_bounds__(512)
void scan3_k(const float* __restrict__ dt, const float* __restrict__ u,
             const float* __restrict__ dbc, const float* __restrict__ Alog,
             const float* __restrict__ hin, const float* __restrict__ xz,
             const float* __restrict__ Dskip, float* __restrict__ yg)
{
    const int t = threadIdx.x;
    const int dl = t >> 4, s = t & 15;
    const int d = blockIdx.x * 32 + dl;
    const int c = blockIdx.y;
    const float A = -__expf(Alog[d * DS + s]);
    const float Dv = Dskip[d];
    const int l0 = c * CLEN;
    const float* pdt = dt  + (size_t)l0 * DI + d;
    const float* pu  = u   + (size_t)l0 * DI + d;
    const float* pB  = dbc + (size_t)l0 * NXPAD + DTR + s;
    const float* pC  = dbc + (size_t)l0 * NXPAD + DTR + DS + s;
    float h = hin[(size_t)c * (DI * DS) + d * DS + s];
#pragma unroll 2
    for (int i = 0; i < CLEN; i++) {
        const float dtv = pdt[i * DI];
        const float uv  = pu [i * DI];
        const float Bv  = pB [i * NXPAD];
        const float Cv  = pC [i * NXPAD];
        const float a = __expf(A * dtv);
        const float b = dtv * Bv * uv;
        h = a * h + b;
        float p = h * Cv;
        p += __shfl_xor_sync(0xffffffffu, p, 8);
        p += __shfl_xor_sync(0xffffffffu, p, 4);
        p += __shfl_xor_sync(0xffffffffu, p, 2);
        p += __shfl_xor_sync(0xffffffffu, p, 1);
        if (s == 0) {
            const int l = l0 + i;
            const float zv  = xz[(size_t)l * (2 * DI) + DI + d];
            const float sig = 1.f / (1.f + __expf(-zv));
            yg[(size_t)l * DI + d] = (p + uv * Dv) * (zv * sig);
        }
    }
}

// ---------------- host ----------------
static float* symaddr(const void* sym)
{
    void* p = nullptr;
    cudaGetSymbolAddress(&p, sym);
    return (float*)p;
}

extern "C" void kernel_launch(void* const* d_in, const int* in_sizes, int n_in,
                              void* d_out, int out_size)
{
    const float* x     = (const float*)d_in[0];
    const float* adj   = (const float*)d_in[1];
    const float* gcn_w = (const float*)d_in[2];
    const float* gcn_b = (const float*)d_in[3];
    const float* ln_g  = (const float*)d_in[4];
    const float* ln_b  = (const float*)d_in[5];
    const float* w_in  = (const float*)d_in[6];
    const float* conv_w= (const float*)d_in[7];
    const float* conv_b= (const float*)d_in[8];
    const float* w_xp  = (const float*)d_in[9];
    const float* w_dt  = (const float*)d_in[10];
    const float* b_dt  = (const float*)d_in[11];
    const float* A_log = (const float*)d_in[12];
    const float* D_skip= (const float*)d_in[13];
    const float* w_out = (const float*)d_in[14];
    float* out = (float*)d_out;

    float* part = symaddr(g_part);
    float* hln  = symaddr(g_hln);
    float* t0   = symaddr(g_t0);
    float* xz   = symaddr(g_xz);
    float* u    = symaddr(g_u);
    float* wxpp = symaddr(g_wxpp);
    float* dbc  = symaddr(g_dbc);
    float* dt   = symaddr(g_dt);
    float* cP   = symaddr(g_cP);
    float* cS   = symaddr(g_cS);
    float* hin  = symaddr(g_hin);
    float* yg   = symaddr(g_yg);

    cudaFuncSetAttribute(mma_gemm, cudaFuncAttributeMaxDynamicSharedMemorySize, MMA_SMEM);

    // 0) pad w_xp to N=128
    padw_k<<<(DI * NXPAD) / 256, 256>>>(w_xp, wxpp);

    // 1) adj @ x, split-K=8 [K=512 each] -> grid (2,32,8) = 512 CTAs, nch=16
    mma_gemm<<<dim3(DM / BN, LSEQ / BM, 8), NTHR, MMA_SMEM>>>(
        adj, x, part, LSEQ / 8, DM, LSEQ, (size_t)LSEQ * DM);
    reduce_k<<<(LSEQ * DM) / 1024, 256>>>(part, t0, (size_t)LSEQ * DM, 8);

    // 2) t0 @ gcn_w, split-K=4 [K=64 each] -> grid 256
    mma_gemm<<<dim3(DM / BN, LSEQ / BM, 4), NTHR, MMA_SMEM>>>(
        t0, gcn_w, part, DM / 4, DM, DM, (size_t)LSEQ * DM);
    // 3) fused 4-partial sum + bias + relu + layernorm
    ln_k<<<LSEQ, 256>>>(part, gcn_b, ln_g, ln_b, hln);

    // 4) xz = hln @ w_in -> grid (8,32) = 256 CTAs, nch=8
    mma_gemm<<<dim3((2 * DI) / BN, LSEQ / BM, 1), NTHR, MMA_SMEM>>>(
        hln, w_in, xz, DM, 2 * DI, DM, 0);
    // 5) u = silu(conv(xc) + b)
    conv_silu_k<<<(LSEQ * DI) / 256, 256>>>(xz, conv_w, conv_b, u);

    // 6) dbc = u @ w_xp (N=128 padded), split-K=8 -> grid 256
    mma_gemm<<<dim3(NXPAD / BN, LSEQ / BM, 8), NTHR, MMA_SMEM>>>(
        u, wxpp, part, DI / 8, NXPAD, DI, (size_t)LSEQ * NXPAD);
    reduce_k<<<(LSEQ * NXPAD) / 1024, 256>>>(part, dbc, (size_t)LSEQ * NXPAD, 8);

    // 7) dt
    dt_k<<<(LSEQ * DI) / 256, 256>>>(dbc, w_dt, b_dt, dt);
    // 8-10) chunked selective scan
    scan1_k<<<dim3(DI / 32, NC), 512>>>(dt, u, dbc, A_log, cP, cS);
    scan2_k<<<(DI * DS) / 512, 512>>>(cP, cS, hin);
    scan3_k<<<dim3(DI / 32, NC), 512>>>(dt, u, dbc, A_log, hin, xz, D_skip, yg);

    // 11) out = yg @ w_out, split-K=4 [K=128 each] -> grid 256, nch=4
    mma_gemm<<<dim3(DM / BN, LSEQ / BM, 4), NTHR, MMA_SMEM>>>(
        yg, w_out, part, DI / 4, DM, DI, (size_t)LSEQ * DM);
    reduce_k<<<(LSEQ * DM) / 1024, 256>>>(part, out, (size_t)LSEQ * DM, 4);
}